// round 5
// baseline (speedup 1.0000x reference)
#include <cuda_runtime.h>
#include <math.h>

// ---------------- problem constants ----------------
#define BATCH   262144
#define DMEM    100
#define NBLK    4096          // BATCH / 64
#define GCOLS   400
#define KTOT    404           // [mem[src](100), mem[dst](100), msg(4), t_enc(100), h(100)]

typedef unsigned long long u64;

// ---------------- scratch (static device globals; no allocation) ----------------
__device__ float g_scr[104857600];   // BATCH x 400
__device__ float a_scr[16777216];    // BATCH x 64
__device__ float Wbig2[49 * 4096];   // 7cc x 7kb tiles, each [32 kp][32 c2][4]
__device__ float B400[400];          // fused biases
__device__ float p_sum[64 * NBLK];   // [ch][block]  (transposed for coalesced reduce)
__device__ float p_sq[64 * NBLK];
__device__ float Ssum[64];
__device__ float Ssq[64];
__device__ float W2e[128];
__device__ float b2e[2];

// ---------------- f32x2 packed-FMA helpers (sm_103a) ----------------
__device__ __forceinline__ void fma2(u64 &d, u64 a, u64 b) {
    asm("fma.rn.f32x2 %0, %1, %2, %0;" : "+l"(d) : "l"(a), "l"(b));
}
__device__ __forceinline__ float2 upk2(u64 v) {
    float2 f; asm("mov.b64 {%0, %1}, %2;" : "=f"(f.x), "=f"(f.y) : "l"(v)); return f;
}
// 128-bit view that lands directly in two u64 register pairs (no packing movs)
struct alignas(16) U64x2 { u64 a, b; };

// accurate cos via fp32 Cody-Waite 3-term (|x| < ~2e5)
__device__ __forceinline__ float cos_acc(float x) {
    const float INV2PI = 0.15915494309189534f;
    const float C1 = 6.28125f;
    const float C2 = 1.934051513671875e-3f;
    const float C3 = 1.2556659146021878e-6f;
    float k = rintf(x * INV2PI);
    float r = fmaf(k, -C1, x);
    r = fmaf(k, -C2, r);
    r = fmaf(k, -C3, r);
    return cosf(r);
}

// ---------------- K0: pack weights (pair-k tiled layout) + biases ----------------
// Wbig2 tile (cc,kb): [kp 0..31][c2 0..31][e 0..3]
//   e: bit0 = k parity, bit1 = c parity
//   k = kb*64 + 2*kp + (e&1), c = cc*64 + 2*c2 + (e>>1)
__global__ void k0_prep(const float* __restrict__ W_ih, const float* __restrict__ W_hh,
                        const float* __restrict__ b_ih, const float* __restrict__ b_hh) {
    int idx0 = blockIdx.x * blockDim.x + threadIdx.x;
    int stride = gridDim.x * blockDim.x;
    for (int idx = idx0; idx < 49 * 4096; idx += stride) {
        int t   = idx >> 12;
        int cc  = t / 7, kb = t - cc * 7;
        int rem = idx & 4095;
        int kp  = rem >> 7;
        int c2  = (rem >> 2) & 31;
        int e   = rem & 3;
        int k = (kb << 6) + (kp << 1) + (e & 1);
        int c = (cc << 6) + (c2 << 1) + (e >> 1);
        float v = 0.f;
        if (c < GCOLS && k < KTOT) {
            if (k < 304) {
                if (c < 300) v = W_ih[c * 304 + k];
            } else {
                int kh = k - 304;
                if (c < 200)       v = W_hh[c * 100 + kh];
                else if (c >= 300) v = W_hh[(c - 100) * 100 + kh];
            }
        }
        Wbig2[idx] = v;
    }
    if (idx0 < 400) {
        int c = idx0;
        float bv;
        if (c < 200)      bv = b_ih[c] + b_hh[c];
        else if (c < 300) bv = b_ih[c];
        else              bv = b_hh[c - 100];
        B400[c] = bv;
    }
}

// ---------------- K1: gather + t_enc + big GEMM (G = U @ W) ----------------
// 256 threads, 64 rows/block. U [64][404] row-major (+64 zero pad),
// W double-buffered pair-tiles [2][4096]. 4x4 microtile, k-paired FFMA2,
// zero packing instructions.
#define USH_FLOATS   (64 * 404 + 64)
#define SMEM1_FLOATS (USH_FLOATS + 2 * 4096 + 200)

__global__ void __launch_bounds__(256, 1)
k1_gemm(const int* __restrict__ n_id, const float* __restrict__ memory,
        const int* __restrict__ last_update, const int* __restrict__ store_src,
        const int* __restrict__ store_dst, const int* __restrict__ store_t,
        const float* __restrict__ store_msg, const float* __restrict__ time_w,
        const float* __restrict__ time_b) {
    extern __shared__ float sh[];
    float* Ush = sh;                       // [64][404] + 64 pad
    float* Wt  = sh + USH_FLOATS;          // [2][4096]
    float* stw = Wt + 2 * 4096;            // [100]
    float* stb = stw + 100;                // [100]
    __shared__ int   s_src[64], s_dst[64], s_nid[64];
    __shared__ float s_dt[64];

    const int tid  = threadIdx.x;
    const int row0 = blockIdx.x << 6;

    if (tid < 64) {
        int nid = n_id[row0 + tid];
        s_nid[tid] = nid;
        s_src[tid] = store_src[nid];
        s_dst[tid] = store_dst[nid];
        s_dt[tid]  = (float)(store_t[nid] - last_update[nid]);
        Ush[64 * 404 + tid] = 0.f;          // tail pad (row-63 overflow reads)
    }
    if (tid < 100) { stw[tid] = time_w[tid]; stb[tid] = time_b[tid]; }
    __syncthreads();

    // build U tile
    for (int i = tid; i < 6400; i += 256) {
        int r = i / 100;
        int c = i - r * 100;
        Ush[r * KTOT + c]        = memory[(size_t)s_src[r] * DMEM + c];
        Ush[r * KTOT + 100 + c]  = memory[(size_t)s_dst[r] * DMEM + c];
        Ush[r * KTOT + 304 + c]  = memory[(size_t)s_nid[r] * DMEM + c];
        float arg = __fadd_rn(__fmul_rn(s_dt[r], stw[c]), stb[c]);
        Ush[r * KTOT + 204 + c]  = cos_acc(arg);
    }
    { // msg
        int r = tid >> 2, m = tid & 3;
        Ush[r * KTOT + 200 + m] = store_msg[(size_t)s_nid[r] * 4 + m];
    }

    const int tx = tid & 15;
    const int ty = tid >> 4;

    // prefetch tile (cc=0, kb=0)
    {
        const float4* src = (const float4*)&Wbig2[0];
        #pragma unroll
        for (int t = 0; t < 4; t++)
            ((float4*)Wt)[tid + (t << 8)] = src[tid + (t << 8)];
    }
    __syncthreads();

    u64 acc[4][4];
    #pragma unroll
    for (int i = 0; i < 4; i++)
        #pragma unroll
        for (int j = 0; j < 4; j++) acc[i][j] = 0ULL;

    int cc = 0, kb = 0, buf = 0;
    while (true) {
        int ncc = cc, nkb = kb + 1;
        if (nkb > 6) { ncc = cc + 1; nkb = (ncc >= 5) ? 4 : 0; }
        const bool has_next = (ncc < 7);

        // LDG next tile into regs
        float4 wr[4];
        if (has_next) {
            const float4* src = (const float4*)&Wbig2[(size_t)(ncc * 7 + nkb) * 4096];
            #pragma unroll
            for (int t = 0; t < 4; t++) wr[t] = src[tid + (t << 8)];
        }

        // compute current tile: 64 k's, paired
        {
            const int kk = kb << 6;
            const float* Wb = Wt + buf * 4096;
            const float* Ub = Ush + (ty << 2) * KTOT + kk;
            #pragma unroll 8
            for (int q = 0; q < 16; q++) {
                // w: kp = 2q (lanes k, k+1), kp = 2q+1 (lanes k+2, k+3)
                U64x2 wa = *(const U64x2*)&Wb[(q << 8) + (tx << 2)];          // cols 2tx,2tx+1 @k
                U64x2 wb = *(const U64x2*)&Wb[(q << 8) + ((tx + 16) << 2)];   // cols +32    @k
                U64x2 wc = *(const U64x2*)&Wb[(q << 8) + 128 + (tx << 2)];    // cols 2tx    @k+2
                U64x2 wd = *(const U64x2*)&Wb[(q << 8) + 128 + ((tx + 16) << 2)];
                #pragma unroll
                for (int r = 0; r < 4; r++) {
                    U64x2 u = *(const U64x2*)&Ub[r * KTOT + (q << 2)];
                    fma2(acc[r][0], u.a, wa.a);
                    fma2(acc[r][1], u.a, wa.b);
                    fma2(acc[r][2], u.a, wb.a);
                    fma2(acc[r][3], u.a, wb.b);
                    fma2(acc[r][0], u.b, wc.a);
                    fma2(acc[r][1], u.b, wc.b);
                    fma2(acc[r][2], u.b, wd.a);
                    fma2(acc[r][3], u.b, wd.b);
                }
            }
        }

        // end of this cc? reduce lane pairs, store, reset
        if (kb == 6) {
            const int c0 = (cc << 6) + (tx << 1);
            const int c1 = c0 + 32;
            #pragma unroll
            for (int r = 0; r < 4; r++) {
                float* gp = &g_scr[(size_t)(row0 + (ty << 2) + r) * GCOLS];
                if (c0 < GCOLS) {
                    float2 e0 = upk2(acc[r][0]);
                    float2 e1 = upk2(acc[r][1]);
                    *(float2*)&gp[c0] = make_float2(e0.x + e0.y, e1.x + e1.y);
                }
                if (c1 < GCOLS) {
                    float2 e2 = upk2(acc[r][2]);
                    float2 e3 = upk2(acc[r][3]);
                    *(float2*)&gp[c1] = make_float2(e2.x + e2.y, e3.x + e3.y);
                }
            }
            #pragma unroll
            for (int i = 0; i < 4; i++)
                #pragma unroll
                for (int j = 0; j < 4; j++) acc[i][j] = 0ULL;
        }

        if (!has_next) break;

        #pragma unroll
        for (int t = 0; t < 4; t++)
            ((float4*)(Wt + (buf ^ 1) * 4096))[tid + (t << 8)] = wr[t];
        __syncthreads();
        buf ^= 1; cc = ncc; kb = nkb;
    }
}

// ---------------- K2: GRU elementwise + MLP GEMM + BN partial sums ----------------
#define K2S 68
#define SMEM2_FLOATS (100 * K2S + 100 * K2S + 1024)

__global__ void __launch_bounds__(256, 1)
k2_gru(const int* __restrict__ n_id, const float* __restrict__ memory,
       const float* __restrict__ W1, const float* __restrict__ b1) {
    extern __shared__ float sh[];
    float* hn  = sh;                 // [100][68] k-major h_new
    float* W1s = sh + 100 * K2S;     // [100][68] k-major W1
    float* red = sh + 200 * K2S;     // [16][64]
    __shared__ int s_nid[64];

    const int tid  = threadIdx.x;
    const int row0 = blockIdx.x << 6;

    if (tid < 64) s_nid[tid] = n_id[row0 + tid];
    for (int i = tid; i < 6400; i += 256) {
        int ch = i / 100, k = i - ch * 100;
        W1s[k * K2S + ch] = W1[i];
    }
    __syncthreads();

    for (int i = tid; i < 6400; i += 256) {
        int r = i / 100, j = i - r * 100;
        const float* g = &g_scr[(size_t)(row0 + r) * GCOLS];
        float h  = memory[(size_t)s_nid[r] * DMEM + j];
        float xr = g[j]       + B400[j];
        float xz = g[100 + j] + B400[100 + j];
        float xn = g[200 + j] + B400[200 + j];
        float xh = g[300 + j] + B400[300 + j];
        float rr = 1.f / (1.f + expf(-xr));
        float zz = 1.f / (1.f + expf(-xz));
        float nn = tanhf(fmaf(rr, xh, xn));
        hn[j * K2S + r] = (1.f - zz) * nn + zz * h;
    }
    __syncthreads();

    const int tx = tid & 15, ty = tid >> 4;
    float acc[4][4];
    #pragma unroll
    for (int i = 0; i < 4; i++)
        #pragma unroll
        for (int j = 0; j < 4; j++) acc[i][j] = 0.f;

    const float* hp = &hn[ty << 2];
    const float* wp = &W1s[tx << 2];
    #pragma unroll 4
    for (int k = 0; k < 100; k++) {
        float4 u = *(const float4*)(hp + k * K2S);
        float4 w = *(const float4*)(wp + k * K2S);
        acc[0][0] = fmaf(u.x, w.x, acc[0][0]); acc[0][1] = fmaf(u.x, w.y, acc[0][1]);
        acc[0][2] = fmaf(u.x, w.z, acc[0][2]); acc[0][3] = fmaf(u.x, w.w, acc[0][3]);
        acc[1][0] = fmaf(u.y, w.x, acc[1][0]); acc[1][1] = fmaf(u.y, w.y, acc[1][1]);
        acc[1][2] = fmaf(u.y, w.z, acc[1][2]); acc[1][3] = fmaf(u.y, w.w, acc[1][3]);
        acc[2][0] = fmaf(u.z, w.x, acc[2][0]); acc[2][1] = fmaf(u.z, w.y, acc[2][1]);
        acc[2][2] = fmaf(u.z, w.z, acc[2][2]); acc[2][3] = fmaf(u.z, w.w, acc[2][3]);
        acc[3][0] = fmaf(u.w, w.x, acc[3][0]); acc[3][1] = fmaf(u.w, w.y, acc[3][1]);
        acc[3][2] = fmaf(u.w, w.z, acc[3][2]); acc[3][3] = fmaf(u.w, w.w, acc[3][3]);
    }

    float bb0 = b1[(tx << 2) + 0], bb1 = b1[(tx << 2) + 1];
    float bb2 = b1[(tx << 2) + 2], bb3 = b1[(tx << 2) + 3];
    float ls[4] = {0.f, 0.f, 0.f, 0.f}, lq[4] = {0.f, 0.f, 0.f, 0.f};
    #pragma unroll
    for (int i = 0; i < 4; i++) {
        float v0 = fmaxf(acc[i][0] + bb0, 0.f);
        float v1 = fmaxf(acc[i][1] + bb1, 0.f);
        float v2 = fmaxf(acc[i][2] + bb2, 0.f);
        float v3 = fmaxf(acc[i][3] + bb3, 0.f);
        *(float4*)&a_scr[(size_t)(row0 + (ty << 2) + i) * 64 + (tx << 2)] =
            make_float4(v0, v1, v2, v3);
        ls[0] += v0; ls[1] += v1; ls[2] += v2; ls[3] += v3;
        lq[0] += v0 * v0; lq[1] += v1 * v1; lq[2] += v2 * v2; lq[3] += v3 * v3;
    }

    #pragma unroll
    for (int j = 0; j < 4; j++) red[ty * 64 + (tx << 2) + j] = ls[j];
    __syncthreads();
    if (tid < 64) {
        float s = 0.f;
        #pragma unroll
        for (int t = 0; t < 16; t++) s += red[t * 64 + tid];
        p_sum[(size_t)tid * NBLK + blockIdx.x] = s;
    }
    __syncthreads();
    #pragma unroll
    for (int j = 0; j < 4; j++) red[ty * 64 + (tx << 2) + j] = lq[j];
    __syncthreads();
    if (tid < 64) {
        float s = 0.f;
        #pragma unroll
        for (int t = 0; t < 16; t++) s += red[t * 64 + tid];
        p_sq[(size_t)tid * NBLK + blockIdx.x] = s;
    }
}

// ---------------- K3a: parallel BN reduction (64 blocks, one per channel) ----------------
__global__ void __launch_bounds__(256) k3_red() {
    __shared__ float rs[256], rq[256];
    const int tid = threadIdx.x, ch = blockIdx.x;
    float s = 0.f, q = 0.f;
    for (int b = tid; b < NBLK; b += 256) {
        s += p_sum[(size_t)ch * NBLK + b];
        q += p_sq[(size_t)ch * NBLK + b];
    }
    rs[tid] = s; rq[tid] = q;
    __syncthreads();
    for (int off = 128; off; off >>= 1) {
        if (tid < off) { rs[tid] += rs[tid + off]; rq[tid] += rq[tid + off]; }
        __syncthreads();
    }
    if (tid == 0) { Ssum[ch] = rs[0]; Ssq[ch] = rq[0]; }
}

// ---------------- K3b: finalize BN stats, fold into W2/b2 ----------------
__global__ void k3_stats2(const float* __restrict__ W2, const float* __restrict__ b2,
                          const float* __restrict__ gamma, const float* __restrict__ beta) {
    __shared__ float sscale[64], sshift[64];
    int tid = threadIdx.x;
    if (tid < 64) {
        const float invN = 1.f / 262144.f;
        float mu  = Ssum[tid] * invN;
        float var = fmaxf(Ssq[tid] * invN - mu * mu, 0.f);
        float sc  = rsqrtf(var + 1e-5f) * gamma[tid];
        sscale[tid] = sc;
        sshift[tid] = beta[tid] - mu * sc;
    }
    __syncthreads();
    if (tid < 128) W2e[tid] = W2[tid] * sscale[tid & 63];
    if (tid < 2) {
        float acc = b2[tid];
        for (int j = 0; j < 64; j++) acc += sshift[j] * W2[tid * 64 + j];
        b2e[tid] = acc;
    }
}

// ---------------- K3c: out = a @ W2e^T + b2e ----------------
__global__ void __launch_bounds__(256) k3_out(float* __restrict__ out) {
    __shared__ float w2s[128];
    __shared__ float b2s[2];
    int tid = threadIdx.x;
    if (tid < 128) w2s[tid] = W2e[tid];
    if (tid < 2)   b2s[tid] = b2e[tid];
    __syncthreads();
    size_t row = (size_t)blockIdx.x * 256 + tid;
    const float4* ap = (const float4*)&a_scr[row * 64];
    float o0 = b2s[0], o1 = b2s[1];
    #pragma unroll
    for (int q4 = 0; q4 < 16; q4++) {
        float4 v = ap[q4];
        int j = q4 * 4;
        o0 += v.x * w2s[j] + v.y * w2s[j + 1] + v.z * w2s[j + 2] + v.w * w2s[j + 3];
        o1 += v.x * w2s[64 + j] + v.y * w2s[64 + j + 1] + v.z * w2s[64 + j + 2] + v.w * w2s[64 + j + 3];
    }
    out[row * 2]     = o0;
    out[row * 2 + 1] = o1;
}

// ---------------- launch ----------------
extern "C" void kernel_launch(void* const* d_in, const int* in_sizes, int n_in,
                              void* d_out, int out_size) {
    const int*   n_id        = (const int*)d_in[0];
    const float* memory      = (const float*)d_in[1];
    const int*   last_update = (const int*)d_in[2];
    const int*   store_src   = (const int*)d_in[3];
    const int*   store_dst   = (const int*)d_in[4];
    const int*   store_t     = (const int*)d_in[5];
    const float* store_msg   = (const float*)d_in[6];
    const float* time_w      = (const float*)d_in[7];
    const float* time_b      = (const float*)d_in[8];
    const float* W_ih        = (const float*)d_in[9];
    const float* b_ih        = (const float*)d_in[10];
    const float* W_hh        = (const float*)d_in[11];
    const float* b_hh        = (const float*)d_in[12];
    const float* W1          = (const float*)d_in[13];
    const float* b1          = (const float*)d_in[14];
    const float* gamma       = (const float*)d_in[15];
    const float* beta        = (const float*)d_in[16];
    const float* W2          = (const float*)d_in[17];
    const float* b2          = (const float*)d_in[18];
    float* out = (float*)d_out;

    const int smem1 = SMEM1_FLOATS * 4;   // ~137 KB
    const int smem2 = SMEM2_FLOATS * 4;   // ~58.5 KB
    cudaFuncSetAttribute(k1_gemm, cudaFuncAttributeMaxDynamicSharedMemorySize, smem1);
    cudaFuncSetAttribute(k2_gru,  cudaFuncAttributeMaxDynamicSharedMemorySize, smem2);

    k0_prep<<<784, 256>>>(W_ih, W_hh, b_ih, b_hh);
    k1_gemm<<<NBLK, 256, smem1>>>(n_id, memory, last_update, store_src, store_dst,
                                  store_t, store_msg, time_w, time_b);
    k2_gru<<<NBLK, 256, smem2>>>(n_id, memory, W1, b1);
    k3_red<<<64, 256>>>();
    k3_stats2<<<1, 128>>>(W2, b2, gamma, beta);
    k3_out<<<1024, 256>>>(out);
}

// round 10
// speedup vs baseline: 2.0913x; 2.0913x over previous
#include <cuda_runtime.h>
#include <cuda_bf16.h>
#include <math.h>
#include <stdint.h>

// ---------------- problem constants ----------------
#define BATCH   262144
#define DMEM    100
#define NBLK    4096          // BATCH / 64  (k1a/k2 blocks)
#define NTILE   2048          // BATCH / 128 (k1b tiles)
#define KTOT    404           // [src(100), dst(100), msg(4), t_enc(100), h(100)]
// K padded to 416 = 26 k16-steps. N logical 400, ordered n = 4*j + gate.

// ---------------- scratch (static device globals; no allocation) ----------------
__device__ float hn_scr[26214400];     // BATCH x 100 h_new
__device__ float a_scr[16777216];      // BATCH x 64
__device__ uint4 upk[27262976];        // A frags: [tile][term][mslice 8][kc 26][lane 32] x16B
__device__ uint4 Wpk4[41600];          // B frags: [term][kc 26][npair 25][lane 32] x16B
__device__ float B400[400];            // fused biases (c = gate*100 + j)
__device__ float p_sum[64 * NBLK];
__device__ float p_sq[64 * NBLK];
__device__ float Ssum[64];
__device__ float Ssq[64];
__device__ float W2e[128];
__device__ float b2e[2];

// ---------------- helpers ----------------
// accurate cos via fp32 Cody-Waite 3-term (|x| < ~2e5)
__device__ __forceinline__ float cos_acc(float x) {
    const float INV2PI = 0.15915494309189534f;
    const float C1 = 6.28125f;
    const float C2 = 1.934051513671875e-3f;
    const float C3 = 1.2556659146021878e-6f;
    float k = rintf(x * INV2PI);
    float r = fmaf(k, -C1, x);
    r = fmaf(k, -C2, r);
    r = fmaf(k, -C3, r);
    return cosf(r);
}

// W element for logical col n = 4*j + gate  ->  c = gate*100 + j
__device__ __forceinline__ float w_elem_log(int k, int n,
                                            const float* W_ih, const float* W_hh) {
    int gate = n & 3, j = n >> 2;
    int c = gate * 100 + j;
    if (k >= KTOT) return 0.f;
    if (k < 304) {
        return (c < 300) ? W_ih[c * 304 + k] : 0.f;
    } else {
        int kh = k - 304;
        if (c < 200)  return W_hh[c * 100 + kh];
        if (c >= 300) return W_hh[(c - 100) * 100 + kh];
        return 0.f;
    }
}

#define MMA16816(acc, a, b0, b1)                                               \
    asm volatile(                                                              \
        "mma.sync.aligned.m16n8k16.row.col.f32.bf16.bf16.f32 "                 \
        "{%0,%1,%2,%3}, {%4,%5,%6,%7}, {%8,%9}, {%0,%1,%2,%3};"                \
        : "+f"((acc)[0]), "+f"((acc)[1]), "+f"((acc)[2]), "+f"((acc)[3])       \
        : "r"((a).x), "r"((a).y), "r"((a).z), "r"((a).w), "r"(b0), "r"(b1))

// ---------------- K0: pack W into B-fragment layout + biases ----------------
// item idx -> [term][kc][npair][lane]; 16B = b-frags for ntiles 2np, 2np+1.
// b frag order per 8B: (k0, k0+1, k0+8, k0+9), k0 = (lane&3)*2, n = ntile*8 + (lane>>2)
__global__ void k0_prep(const float* __restrict__ W_ih, const float* __restrict__ W_hh,
                        const float* __restrict__ b_ih, const float* __restrict__ b_hh) {
    int idx = blockIdx.x * blockDim.x + threadIdx.x;
    if (idx < 41600) {
        int lane = idx & 31;
        int t2   = idx >> 5;
        int np   = t2 % 25;
        int t3   = t2 / 25;
        int kc   = t3 % 26;
        int term = t3 / 26;
        __nv_bfloat16 h2[8];
        int k0l = (lane & 3) * 2;
        int koff[4] = {k0l, k0l + 1, k0l + 8, k0l + 9};
        #pragma unroll
        for (int h = 0; h < 2; h++) {
            int n = (np * 2 + h) * 8 + (lane >> 2);
            #pragma unroll
            for (int e = 0; e < 4; e++) {
                int k = kc * 16 + koff[e];
                float v = w_elem_log(k, n, W_ih, W_hh);
                __nv_bfloat16 hi = __float2bfloat16(v);
                h2[h * 4 + e] = (term == 0) ? hi
                              : __float2bfloat16(v - __bfloat162float(hi));
            }
        }
        Wpk4[idx] = *(const uint4*)h2;
    }
    if (idx < 400) {
        int c = idx;
        float bv;
        if (c < 200)      bv = b_ih[c] + b_hh[c];
        else if (c < 300) bv = b_ih[c];
        else              bv = b_hh[c - 100];
        B400[c] = bv;
    }
}

// ---------------- K1a: gather + cos + bf16 split -> A-fragment tiles ----------------
// 4096 blocks x 256 threads, 64 rows (4 m16-slices, half of a 128-row tile).
// SMEM: [term 2][mslice 4][kc 26][512B] = 106496 B
#define SMEM1A 106496

__device__ __forceinline__ void u_store(char* sm, int rl, int k, float v) {
    int ms = rl >> 4, r = rl & 15;
    int kc = k >> 4, kl = k & 15;
    int lane = ((r & 7) << 2) | ((kl >> 1) & 3);
    int e    = (kl & 1) | ((r >> 3) << 1) | (((kl >> 3) & 1) << 2);
    int base = ((ms * 26 + kc) << 9) + (lane << 4) + (e << 1);
    __nv_bfloat16 hi = __float2bfloat16(v);
    *(__nv_bfloat16*)(sm + base) = hi;
    *(__nv_bfloat16*)(sm + 53248 + base) = __float2bfloat16(v - __bfloat162float(hi));
}

__global__ void __launch_bounds__(256, 1)
k1a_pack(const int* __restrict__ n_id, const float* __restrict__ memory,
         const int* __restrict__ last_update, const int* __restrict__ store_src,
         const int* __restrict__ store_dst, const int* __restrict__ store_t,
         const float* __restrict__ store_msg, const float* __restrict__ time_w,
         const float* __restrict__ time_b) {
    extern __shared__ char sm[];
    __shared__ int   s_src[64], s_dst[64], s_nid[64];
    __shared__ float s_dt[64], stw[100], stb[100];

    const int tid  = threadIdx.x;
    const int blk  = blockIdx.x;
    const int row0 = blk << 6;
    const int tile = blk >> 1;
    const int half = blk & 1;

    if (tid < 64) {
        int nid = n_id[row0 + tid];
        s_nid[tid] = nid;
        s_src[tid] = store_src[nid];
        s_dst[tid] = store_dst[nid];
        s_dt[tid]  = (float)(store_t[nid] - last_update[nid]);
    }
    if (tid < 100) { stw[tid] = time_w[tid]; stb[tid] = time_b[tid]; }
    for (int i = tid; i < 26624; i += 256) ((uint32_t*)sm)[i] = 0u;
    __syncthreads();

    for (int i = tid; i < 6400; i += 256) {
        int r = i / 100, c = i - r * 100;
        u_store(sm, r, c,       memory[(size_t)s_src[r] * DMEM + c]);
        u_store(sm, r, 100 + c, memory[(size_t)s_dst[r] * DMEM + c]);
        u_store(sm, r, 304 + c, memory[(size_t)s_nid[r] * DMEM + c]);
        float arg = __fadd_rn(__fmul_rn(s_dt[r], stw[c]), stb[c]);
        u_store(sm, r, 204 + c, cos_acc(arg));
    }
    {   // msg: 4 per row
        int r = tid >> 2, m = tid & 3;
        u_store(sm, r, 200 + m, store_msg[(size_t)s_nid[r] * 4 + m]);
    }
    __syncthreads();

    // linear copy-out: upk[((tile*2 + term)*8 + mslice)*832 + ...]
    #pragma unroll
    for (int t = 0; t < 2; t++)
        #pragma unroll
        for (int m = 0; m < 4; m++) {
            const uint4* s = (const uint4*)(sm + (size_t)(t * 4 + m) * 13312);
            uint4* d = upk + (((size_t)tile * 2 + t) * 8 + half * 4 + m) * 832;
            for (int i = tid; i < 832; i += 256) d[i] = s[i];
        }
}

// ---------------- K1b: mma.sync bf16 GEMM (3-term split) + fused GRU ----------------
// 2048 CTAs x 256 thr. 128 rows/CTA, 8 warps (16 rows each).
// N processed in 5 tiles of 80 cols (10 n8-tiles). acc = 40 fp32 regs.
// SMEM (dynamic 66560B): B stage [26 kc][5 np][512B]; overlaid by G dump 128x80 fp32.
#define SMEM1B 66560

__global__ void __launch_bounds__(256, 2)
k1b_mma(const int* __restrict__ n_id, const float* __restrict__ memory) {
    extern __shared__ char sm[];
    uint4* Bs = (uint4*)sm;
    float* Gd = (float*)sm;
    __shared__ float B400s[400];
    __shared__ int   s_nid[128];

    const int tid  = threadIdx.x;
    const int wid  = tid >> 5;
    const int lane = tid & 31;
    const int tile = blockIdx.x;
    const int row0 = tile << 7;

    for (int i = tid; i < 400; i += 256) B400s[i] = B400[i];
    if (tid < 128) s_nid[tid] = n_id[row0 + tid];

    float acc[10][4];

    for (int nt = 0; nt < 5; nt++) {
        #pragma unroll
        for (int q = 0; q < 10; q++)
            #pragma unroll
            for (int e = 0; e < 4; e++) acc[q][e] = 0.f;

        // pass order: (aterm,bterm) = (0,0), (1,0), (0,1)  -> restage only twice
        for (int pp = 0; pp < 3; pp++) {
            const int aterm = (pp == 1) ? 1 : 0;
            const int bterm = (pp == 2) ? 1 : 0;
            if (pp != 1) {
                __syncthreads();
                for (int i = tid; i < 4160; i += 256) {
                    int kc = i / 160, rem = i - kc * 160;
                    Bs[i] = Wpk4[((bterm * 26 + kc) * 25 + nt * 5) * 32 + rem];
                }
                __syncthreads();
            }
            const uint4* Ab = upk + (((size_t)tile * 2 + aterm) * 8 + wid) * 832;
            #pragma unroll 2
            for (int kc = 0; kc < 26; kc++) {
                uint4 a = Ab[kc * 32 + lane];
                #pragma unroll
                for (int np = 0; np < 5; np++) {
                    uint4 b = Bs[kc * 160 + np * 32 + lane];
                    MMA16816(acc[np * 2],     a, b.x, b.y);
                    MMA16816(acc[np * 2 + 1], a, b.z, b.w);
                }
            }
        }

        // dump acc -> SMEM (overlays B stage; restaged next nt)
        __syncthreads();
        {
            int r0 = (wid << 4) + (lane >> 2);
            int c0 = (lane & 3) << 1;
            #pragma unroll
            for (int q = 0; q < 10; q++) {
                int nl = q * 8 + c0;
                *(float2*)&Gd[r0 * 80 + nl]       = make_float2(acc[q][0], acc[q][1]);
                *(float2*)&Gd[(r0 + 8) * 80 + nl] = make_float2(acc[q][2], acc[q][3]);
            }
        }
        __syncthreads();

        // fused GRU for the 20 feature dims of this tile
        for (int i = tid; i < 2560; i += 256) {
            int row = i / 20, jl = i - row * 20;
            int j = nt * 20 + jl;
            float4 g4 = *(const float4*)&Gd[row * 80 + jl * 4];
            float h  = memory[(size_t)s_nid[row] * DMEM + j];
            float xr = g4.x + B400s[j];
            float xz = g4.y + B400s[100 + j];
            float xn = g4.z + B400s[200 + j];
            float xh = g4.w + B400s[300 + j];
            float rr = 1.f / (1.f + expf(-xr));
            float zz = 1.f / (1.f + expf(-xz));
            float nn = tanhf(fmaf(rr, xh, xn));
            hn_scr[(size_t)(row0 + row) * DMEM + j] = (1.f - zz) * nn + zz * h;
        }
    }
}

// ---------------- K2: MLP GEMM + BN partial sums (reads hn_scr) ----------------
#define K2S 68
#define SMEM2_FLOATS (100 * K2S + 100 * K2S + 1024)

__global__ void __launch_bounds__(256, 1)
k2_mlp(const float* __restrict__ W1, const float* __restrict__ b1) {
    extern __shared__ float sh[];
    float* hn  = sh;
    float* W1s = sh + 100 * K2S;
    float* red = sh + 200 * K2S;

    const int tid  = threadIdx.x;
    const int row0 = blockIdx.x << 6;

    for (int i = tid; i < 6400; i += 256) {
        int ch = i / 100, k = i - ch * 100;
        W1s[k * K2S + ch] = W1[i];
    }
    for (int i = tid; i < 6400; i += 256) {
        int r = i / 100, j = i - r * 100;
        hn[j * K2S + r] = hn_scr[(size_t)(row0 + r) * DMEM + j];
    }
    __syncthreads();

    const int tx = tid & 15, ty = tid >> 4;
    float acc[4][4];
    #pragma unroll
    for (int i = 0; i < 4; i++)
        #pragma unroll
        for (int j = 0; j < 4; j++) acc[i][j] = 0.f;

    const float* hp = &hn[ty << 2];
    const float* wp = &W1s[tx << 2];
    #pragma unroll 4
    for (int k = 0; k < 100; k++) {
        float4 u = *(const float4*)(hp + k * K2S);
        float4 w = *(const float4*)(wp + k * K2S);
        acc[0][0] = fmaf(u.x, w.x, acc[0][0]); acc[0][1] = fmaf(u.x, w.y, acc[0][1]);
        acc[0][2] = fmaf(u.x, w.z, acc[0][2]); acc[0][3] = fmaf(u.x, w.w, acc[0][3]);
        acc[1][0] = fmaf(u.y, w.x, acc[1][0]); acc[1][1] = fmaf(u.y, w.y, acc[1][1]);
        acc[1][2] = fmaf(u.y, w.z, acc[1][2]); acc[1][3] = fmaf(u.y, w.w, acc[1][3]);
        acc[2][0] = fmaf(u.z, w.x, acc[2][0]); acc[2][1] = fmaf(u.z, w.y, acc[2][1]);
        acc[2][2] = fmaf(u.z, w.z, acc[2][2]); acc[2][3] = fmaf(u.z, w.w, acc[2][3]);
        acc[3][0] = fmaf(u.w, w.x, acc[3][0]); acc[3][1] = fmaf(u.w, w.y, acc[3][1]);
        acc[3][2] = fmaf(u.w, w.z, acc[3][2]); acc[3][3] = fmaf(u.w, w.w, acc[3][3]);
    }

    float bb0 = b1[(tx << 2) + 0], bb1 = b1[(tx << 2) + 1];
    float bb2 = b1[(tx << 2) + 2], bb3 = b1[(tx << 2) + 3];
    float ls[4] = {0.f, 0.f, 0.f, 0.f}, lq[4] = {0.f, 0.f, 0.f, 0.f};
    #pragma unroll
    for (int i = 0; i < 4; i++) {
        float v0 = fmaxf(acc[i][0] + bb0, 0.f);
        float v1 = fmaxf(acc[i][1] + bb1, 0.f);
        float v2 = fmaxf(acc[i][2] + bb2, 0.f);
        float v3 = fmaxf(acc[i][3] + bb3, 0.f);
        *(float4*)&a_scr[(size_t)(row0 + (ty << 2) + i) * 64 + (tx << 2)] =
            make_float4(v0, v1, v2, v3);
        ls[0] += v0; ls[1] += v1; ls[2] += v2; ls[3] += v3;
        lq[0] += v0 * v0; lq[1] += v1 * v1; lq[2] += v2 * v2; lq[3] += v3 * v3;
    }

    #pragma unroll
    for (int j = 0; j < 4; j++) red[ty * 64 + (tx << 2) + j] = ls[j];
    __syncthreads();
    if (tid < 64) {
        float s = 0.f;
        #pragma unroll
        for (int t = 0; t < 16; t++) s += red[t * 64 + tid];
        p_sum[(size_t)tid * NBLK + blockIdx.x] = s;
    }
    __syncthreads();
    #pragma unroll
    for (int j = 0; j < 4; j++) red[ty * 64 + (tx << 2) + j] = lq[j];
    __syncthreads();
    if (tid < 64) {
        float s = 0.f;
        #pragma unroll
        for (int t = 0; t < 16; t++) s += red[t * 64 + tid];
        p_sq[(size_t)tid * NBLK + blockIdx.x] = s;
    }
}

// ---------------- K3a: parallel BN reduction ----------------
__global__ void __launch_bounds__(256) k3_red() {
    __shared__ float rs[256], rq[256];
    const int tid = threadIdx.x, ch = blockIdx.x;
    float s = 0.f, q = 0.f;
    for (int b = tid; b < NBLK; b += 256) {
        s += p_sum[(size_t)ch * NBLK + b];
        q += p_sq[(size_t)ch * NBLK + b];
    }
    rs[tid] = s; rq[tid] = q;
    __syncthreads();
    for (int off = 128; off; off >>= 1) {
        if (tid < off) { rs[tid] += rs[tid + off]; rq[tid] += rq[tid + off]; }
        __syncthreads();
    }
    if (tid == 0) { Ssum[ch] = rs[0]; Ssq[ch] = rq[0]; }
}

// ---------------- K3b: finalize BN stats, fold into W2/b2 ----------------
__global__ void k3_stats2(const float* __restrict__ W2, const float* __restrict__ b2,
                          const float* __restrict__ gamma, const float* __restrict__ beta) {
    __shared__ float sscale[64], sshift[64];
    int tid = threadIdx.x;
    if (tid < 64) {
        const float invN = 1.f / 262144.f;
        float mu  = Ssum[tid] * invN;
        float var = fmaxf(Ssq[tid] * invN - mu * mu, 0.f);
        float sc  = rsqrtf(var + 1e-5f) * gamma[tid];
        sscale[tid] = sc;
        sshift[tid] = beta[tid] - mu * sc;
    }
    __syncthreads();
    if (tid < 128) W2e[tid] = W2[tid] * sscale[tid & 63];
    if (tid < 2) {
        float acc = b2[tid];
        for (int j = 0; j < 64; j++) acc += sshift[j] * W2[tid * 64 + j];
        b2e[tid] = acc;
    }
}

// ---------------- K3c: out = a @ W2e^T + b2e ----------------
__global__ void __launch_bounds__(256) k3_out(float* __restrict__ out) {
    __shared__ float w2s[128];
    __shared__ float b2s[2];
    int tid = threadIdx.x;
    if (tid < 128) w2s[tid] = W2e[tid];
    if (tid < 2)   b2s[tid] = b2e[tid];
    __syncthreads();
    size_t row = (size_t)blockIdx.x * 256 + tid;
    const float4* ap = (const float4*)&a_scr[row * 64];
    float o0 = b2s[0], o1 = b2s[1];
    #pragma unroll
    for (int q4 = 0; q4 < 16; q4++) {
        float4 v = ap[q4];
        int j = q4 * 4;
        o0 += v.x * w2s[j] + v.y * w2s[j + 1] + v.z * w2s[j + 2] + v.w * w2s[j + 3];
        o1 += v.x * w2s[64 + j] + v.y * w2s[64 + j + 1] + v.z * w2s[64 + j + 2] + v.w * w2s[64 + j + 3];
    }
    out[row * 2]     = o0;
    out[row * 2 + 1] = o1;
}

// ---------------- launch ----------------
extern "C" void kernel_launch(void* const* d_in, const int* in_sizes, int n_in,
                              void* d_out, int out_size) {
    const int*   n_id        = (const int*)d_in[0];
    const float* memory      = (const float*)d_in[1];
    const int*   last_update = (const int*)d_in[2];
    const int*   store_src   = (const int*)d_in[3];
    const int*   store_dst   = (const int*)d_in[4];
    const int*   store_t     = (const int*)d_in[5];
    const float* store_msg   = (const float*)d_in[6];
    const float* time_w      = (const float*)d_in[7];
    const float* time_b      = (const float*)d_in[8];
    const float* W_ih        = (const float*)d_in[9];
    const float* b_ih        = (const float*)d_in[10];
    const float* W_hh        = (const float*)d_in[11];
    const float* b_hh        = (const float*)d_in[12];
    const float* W1          = (const float*)d_in[13];
    const float* b1          = (const float*)d_in[14];
    const float* gamma       = (const float*)d_in[15];
    const float* beta        = (const float*)d_in[16];
    const float* W2          = (const float*)d_in[17];
    const float* b2          = (const float*)d_in[18];
    float* out = (float*)d_out;

    const int smem2 = SMEM2_FLOATS * 4;
    cudaFuncSetAttribute(k1a_pack, cudaFuncAttributeMaxDynamicSharedMemorySize, SMEM1A);
    cudaFuncSetAttribute(k1b_mma,  cudaFuncAttributeMaxDynamicSharedMemorySize, SMEM1B);
    cudaFuncSetAttribute(k2_mlp,   cudaFuncAttributeMaxDynamicSharedMemorySize, smem2);

    k0_prep<<<163, 256>>>(W_ih, W_hh, b_ih, b_hh);
    k1a_pack<<<NBLK, 256, SMEM1A>>>(n_id, memory, last_update, store_src, store_dst,
                                    store_t, store_msg, time_w, time_b);
    k1b_mma<<<NTILE, 256, SMEM1B>>>(n_id, memory);
    k2_mlp<<<NBLK, 256, smem2>>>(W1, b1);
    k3_red<<<64, 256>>>();
    k3_stats2<<<1, 128>>>(W2, b2, gamma, beta);
    k3_out<<<1024, 256>>>(out);
}